// round 10
// baseline (speedup 1.0000x reference)
#include <cuda_runtime.h>
#include <cstddef>

// GCN 2-layer, single persistent kernel with device-wide barriers.
// N=100000, E=3.2M, DIN=128, DH=32, DOUT=2. edge_index int32.

static constexpr int NMAX  = 100000;
static constexpr long long EMAX = 3300000;
static constexpr int D_IN  = 128;
static constexpr int D_H   = 32;
static constexpr int D_OUT = 2;

__device__ __align__(16) float g_dinv[NMAX];
__device__ __align__(16) float g_m1s [(size_t)NMAX * D_H];
__device__ __align__(16) float g_p2  [(size_t)NMAX * D_OUT];
__device__ __align__(16) int   g_cnt[NMAX];
__device__ __align__(16) int   g_off[NMAX];     // becomes END after fill
__device__ int g_adj[EMAX];
__device__ int g_bsum[1024];
__device__ unsigned g_bar_cnt;                  // zero-init; self-resetting
__device__ volatile unsigned g_bar_sense;

// Sense-relative grid barrier: replay-safe (no absolute generation numbers).
__device__ __forceinline__ void gsync(int nblk) {
    __syncthreads();
    if (threadIdx.x == 0) {
        unsigned s0 = g_bar_sense;              // read BEFORE arriving
        __threadfence();                        // order data stores + s0 before arrive
        unsigned old = atomicAdd(&g_bar_cnt, 1u);
        if (old == (unsigned)nblk - 1u) {
            g_bar_cnt = 0u;                     // reset before release
            __threadfence();
            g_bar_sense = s0 + 1u;              // release
        } else {
            while (g_bar_sense == s0) { }
            __threadfence();
        }
    }
    __syncthreads();
}

// 48KB shared: [0,16K) Wp (k-pair interleaved W1^T), [16K,48K) sx tiles.
// Scan phase overlays int sp[256] at offset 0.
__global__ void __launch_bounds__(256, 3)
k_gcn(const float* __restrict__ x, const int* __restrict__ src,
      const int* __restrict__ dst, const float* __restrict__ W1,
      const float* __restrict__ b1, const float* __restrict__ W2,
      const float* __restrict__ b2, float* __restrict__ out,
      int n, int E, int nblk) {
    __shared__ __align__(16) char smem_raw[49152];
    float*  sWp = (float*)smem_raw;
    float4* sxb = (float4*)(smem_raw + 16384);      // [8 warps][8 rows][32 k4]
    int*    sp  = (int*)smem_raw;

    const int tid = threadIdx.x, b = blockIdx.x;
    const int nthreads = nblk * 256;
    const int gt = b * 256 + tid;
    const int warp = tid >> 5, lane = tid & 31;

    // ---- P0: zero degree counts ----
    int n4 = (n + 3) >> 2;
    for (int i = gt; i < n4; i += nthreads)
        ((int4*)g_cnt)[i] = make_int4(0, 0, 0, 0);
    gsync(nblk);

    // ---- P1: count degrees ----
    int e4 = E >> 2;
    for (int i = gt; i < e4; i += nthreads) {
        int4 d = ((const int4*)dst)[i];
        atomicAdd(&g_cnt[d.x], 1); atomicAdd(&g_cnt[d.y], 1);
        atomicAdd(&g_cnt[d.z], 1); atomicAdd(&g_cnt[d.w], 1);
    }
    for (int e = (e4 << 2) + gt; e < E; e += nthreads)
        atomicAdd(&g_cnt[dst[e]], 1);
    gsync(nblk);

    // ---- P2: block-local scan (contiguous chunk of 256*K nodes per block) ----
    int K = (n + nthreads - 1) / nthreads;     // nodes per thread (<=4 here)
    if (K > 4) K = 4;
    int base = (b * 256 + tid) * K;
    int v[4]; int s = 0;
    #pragma unroll
    for (int j = 0; j < 4; j++) {
        int i = base + j;
        v[j] = (j < K && i < n) ? __ldcg(&g_cnt[i]) : 0;   // L2 (skip stale L1)
        s += v[j];
    }
    sp[tid] = s; __syncthreads();
    #pragma unroll
    for (int o = 1; o < 256; o <<= 1) {
        int t = (tid >= o) ? sp[tid - o] : 0;
        __syncthreads();
        sp[tid] += t;
        __syncthreads();
    }
    int incl = sp[tid];
    if (tid == 255) g_bsum[b] = sp[255];
    gsync(nblk);

    // ---- P3: add cross-block prefix, write offsets + dinv ----
    {
        int pre = 0;
        #pragma unroll 4
        for (int j = 0; j < b; j++) pre += g_bsum[j];      // broadcast loads
        int excl = pre + incl - s;
        #pragma unroll
        for (int j = 0; j < 4; j++) {
            int i = base + j;
            if (j < K && i < n) {
                g_off[i]  = excl; excl += v[j];
                g_dinv[i] = rsqrtf((float)v[j] + 1.0f);    // +1 self loop
            }
        }
    }
    gsync(nblk);

    // ---- P4a: layer-1 GEMM (m1s = (x@W1)*dinv), 64-row tiles ----
    for (int i = tid; i < D_IN * D_H; i += 256) {          // W1^T, k-pair packed
        int k = i >> 5, c = i & 31;
        sWp[(k >> 1) * 64 + c * 2 + (k & 1)] = W1[i];
    }
    __syncthreads();
    int ntile = (n + 63) >> 6;
    for (int t = b; t < ntile; t += nblk) {
        int row0 = t * 64 + warp * 8;
        __syncthreads();                                   // protect prev tile's sx
        #pragma unroll
        for (int r = 0; r < 8; r++) {
            int row = row0 + r;
            if (row < n)
                sxb[(warp * 8 + r) * 32 + lane] =
                    ((const float4*)(x + (size_t)row * D_IN))[lane];
        }
        __syncwarp();
        const ulonglong2* sxp = (const ulonglong2*)(sxb + (size_t)warp * 8 * 32);
        const unsigned long long* sWq = (const unsigned long long*)sWp;
        unsigned long long acc[8] = {0ull,0ull,0ull,0ull,0ull,0ull,0ull,0ull};
        #pragma unroll 4
        for (int k4 = 0; k4 < D_IN / 4; k4++) {
            unsigned long long w01 = sWq[(k4 * 2 + 0) * 32 + lane];
            unsigned long long w23 = sWq[(k4 * 2 + 1) * 32 + lane];
            #pragma unroll
            for (int r = 0; r < 8; r++) {
                ulonglong2 xp = sxp[r * 32 + k4];
                asm("fma.rn.f32x2 %0, %1, %2, %0;" : "+l"(acc[r]) : "l"(xp.x), "l"(w01));
                asm("fma.rn.f32x2 %0, %1, %2, %0;" : "+l"(acc[r]) : "l"(xp.y), "l"(w23));
            }
        }
        #pragma unroll
        for (int r = 0; r < 8; r++) {
            int row = row0 + r;
            if (row < n) {
                float lo = __uint_as_float((unsigned)(acc[r] & 0xffffffffull));
                float hi = __uint_as_float((unsigned)(acc[r] >> 32));
                g_m1s[(size_t)row * D_H + lane] = (lo + hi) * g_dinv[row];
            }
        }
    }
    // ---- P4b: CSR fill (same phase; overlaps gemm across blocks) ----
    for (int e = gt; e < E; e += nthreads) {
        int d = dst[e];
        int pos = atomicAdd(&g_off[d], 1);                 // g_off -> END
        g_adj[pos] = src[e];
    }
    gsync(nblk);

    // ---- P5: fused layer-1 gather + layer-2 transform ----
    int nw = nblk * 8;
    for (int w = b * 8 + warp; w < n; w += nw) {
        int cnt = __ldcg(&g_cnt[w]);
        int start = __ldcg(&g_off[w]) - cnt;               // off is END
        float dv = g_dinv[w];
        float a[8] = {0.f,0.f,0.f,0.f,0.f,0.f,0.f,0.f};
        int j = 0;
        for (; j + 32 <= cnt; j += 32) {
            int idx = g_adj[start + j + lane];
            #pragma unroll
            for (int t = 0; t < 32; t += 8) {
                #pragma unroll
                for (int u = 0; u < 8; u++) {
                    int sidx = __shfl_sync(0xffffffffu, idx, t + u);
                    a[u] += g_m1s[(size_t)sidx * D_H + lane];
                }
            }
        }
        if (j < cnt) {
            int rem = cnt - j;
            int idx = (lane < rem) ? g_adj[start + j + lane] : 0;
            int t = 0;
            for (; t + 8 <= rem; t += 8) {
                #pragma unroll
                for (int u = 0; u < 8; u++) {
                    int sidx = __shfl_sync(0xffffffffu, idx, t + u);
                    a[u] += g_m1s[(size_t)sidx * D_H + lane];
                }
            }
            for (; t < rem; t++) {
                int sidx = __shfl_sync(0xffffffffu, idx, t);
                a[t & 7] += g_m1s[(size_t)sidx * D_H + lane];
            }
        }
        float accv = ((a[0]+a[1]) + (a[2]+a[3])) + ((a[4]+a[5]) + (a[6]+a[7]));
        accv += g_m1s[(size_t)w * D_H + lane];             // self loop
        float h = fmaxf(accv * dv + __ldg(&b1[lane]), 0.f);
        float p0 = h * __ldg(&W2[lane * 2 + 0]);
        float p1 = h * __ldg(&W2[lane * 2 + 1]);
        #pragma unroll
        for (int o = 16; o; o >>= 1) {
            p0 += __shfl_xor_sync(0xffffffffu, p0, o);
            p1 += __shfl_xor_sync(0xffffffffu, p1, o);
        }
        if (lane == 0) {
            float q0 = p0 * dv, q1 = p1 * dv;
            g_p2[(size_t)w * 2 + 0] = q0;
            g_p2[(size_t)w * 2 + 1] = q1;
            out[(size_t)w * 2 + 0] = __ldg(&b2[0]) + q0 * dv;
            out[(size_t)w * 2 + 1] = __ldg(&b2[1]) + q1 * dv;
        }
    }
    gsync(nblk);

    // ---- P6: layer-2 gather ----
    for (int w = b * 8 + warp; w < n; w += nw) {
        int cnt = __ldcg(&g_cnt[w]);
        int start = __ldcg(&g_off[w]) - cnt;
        float a0 = 0.f, a1 = 0.f;
        for (int j = lane; j < cnt; j += 32) {
            int sidx = g_adj[start + j];
            float2 p = *(const float2*)(g_p2 + (size_t)sidx * 2);
            a0 += p.x; a1 += p.y;
        }
        #pragma unroll
        for (int o = 16; o; o >>= 1) {
            a0 += __shfl_xor_sync(0xffffffffu, a0, o);
            a1 += __shfl_xor_sync(0xffffffffu, a1, o);
        }
        if (lane == 0) {
            float dv = g_dinv[w];
            out[(size_t)w * 2 + 0] += a0 * dv;
            out[(size_t)w * 2 + 1] += a1 * dv;
        }
    }
}

extern "C" void kernel_launch(void* const* d_in, const int* in_sizes, int n_in,
                              void* d_out, int out_size) {
    const float* x   = (const float*)d_in[0];
    const int*   ei  = (const int*)d_in[1];
    const float* W1  = (const float*)d_in[2];
    const float* b1  = (const float*)d_in[3];
    const float* W2  = (const float*)d_in[4];
    const float* b2  = (const float*)d_in[5];
    float*       out = (float*)d_out;

    int n = in_sizes[0] / D_IN;
    int E = in_sizes[1] / 2;

    int dev = 0, sm = 148;
    cudaGetDevice(&dev);
    cudaDeviceGetAttribute(&sm, cudaDevAttrMultiProcessorCount, dev);
    int nblk = sm * 3;                         // matches __launch_bounds__(256,3)
    if (nblk > 1024) nblk = 1024;              // g_bsum bound

    k_gcn<<<nblk, 256>>>(x, ei, ei + E, W1, b1, W2, b2, out, n, E, nblk);
}

// round 12
// speedup vs baseline: 1.3354x; 1.3354x over previous
#include <cuda_runtime.h>
#include <cstddef>

// GCN 2-layer: CSR build + gather aggregation. N=100000, E=3.2M, 128->32->2.
// edge_index int32. All components from previously passing rounds except the
// fill+gemm block-role fusion (disjoint data; safe).

static constexpr int NMAX  = 100000;
static constexpr long long EMAX = 3300000;
static constexpr int D_IN  = 128;
static constexpr int D_H   = 32;
static constexpr int D_OUT = 2;
static constexpr int SCAN_BLK = 2048;

__device__ __align__(16) float g_dinv[NMAX];
__device__ __align__(16) float g_m1s [(size_t)NMAX * D_H];
__device__ __align__(16) float g_p2  [(size_t)NMAX * D_OUT];
__device__ __align__(16) int   g_cnt[NMAX];
__device__ __align__(16) int   g_off[NMAX];     // exclusive start -> END after fill
__device__ int g_adj[EMAX];
__device__ int g_bsum[(NMAX + SCAN_BLK - 1) / SCAN_BLK];

// ---- P0: zero counts (int4) -------------------------------------------------
__global__ void k_zero(int n4) {
    int i = blockIdx.x * blockDim.x + threadIdx.x;
    if (i < n4) ((int4*)g_cnt)[i] = make_int4(0, 0, 0, 0);
}

// ---- P1: count degrees (int4) ----------------------------------------------
__global__ void k_count(const int* __restrict__ dst, int E) {
    int i = blockIdx.x * blockDim.x + threadIdx.x;
    int e = i * 4;
    if (e + 3 < E) {
        int4 d = *(const int4*)(dst + e);
        atomicAdd(&g_cnt[d.x], 1);
        atomicAdd(&g_cnt[d.y], 1);
        atomicAdd(&g_cnt[d.z], 1);
        atomicAdd(&g_cnt[d.w], 1);
    } else {
        for (; e < E; e++) atomicAdd(&g_cnt[dst[e]], 1);
    }
}

// ---- P2: block-local scan + dinv + block sums -------------------------------
__global__ void __launch_bounds__(256) k_part(int n) {
    __shared__ int sp[256];
    int base = blockIdx.x * SCAN_BLK + threadIdx.x * 8;
    int v[8]; int s = 0;
    #pragma unroll
    for (int j = 0; j < 8; j++) {
        int i = base + j;
        v[j] = (i < n) ? g_cnt[i] : 0;
        s += v[j];
    }
    sp[threadIdx.x] = s; __syncthreads();
    for (int ofs = 1; ofs < 256; ofs <<= 1) {
        int t = (threadIdx.x >= ofs) ? sp[threadIdx.x - ofs] : 0;
        __syncthreads();
        sp[threadIdx.x] += t;
        __syncthreads();
    }
    int excl = threadIdx.x ? sp[threadIdx.x - 1] : 0;
    #pragma unroll
    for (int j = 0; j < 8; j++) {
        int i = base + j;
        if (i < n) {
            g_off[i]  = excl; excl += v[j];
            g_dinv[i] = rsqrtf((float)v[j] + 1.0f);   // +1 self loop
        }
    }
    if (threadIdx.x == 255) g_bsum[blockIdx.x] = sp[255];
}

// ---- P3: add cross-block prefix (each 256-node CTA inside ONE scan block) --
__global__ void k_finoff(int n) {
    int sb = (blockIdx.x * 256) / SCAN_BLK;
    int pre = 0;
    for (int j = 0; j < sb; j++) pre += g_bsum[j];
    int i = blockIdx.x * 256 + threadIdx.x;
    if (i < n) g_off[i] += pre;
}

// ---- P4: fused CSR fill + layer-1 GEMM (disjoint data, block-role split) ---
// bid < nfill: fill (g_off -> END). bid >= nfill: gemm tile (64 rows).
__global__ void __launch_bounds__(256) k_fillgemm(const int* __restrict__ src,
                                                  const int* __restrict__ dst,
                                                  const float* __restrict__ x,
                                                  const float* __restrict__ W1,
                                                  int n, int E, int nfill) {
    __shared__ float  sWp[D_IN * D_H];       // k-pair interleaved W1^T
    __shared__ float4 sx[8][8][D_IN / 4];
    int bid = blockIdx.x;
    if (bid < nfill) {
        int nt = nfill * 256;
        for (int e = bid * 256 + threadIdx.x; e < E; e += nt) {
            int d = dst[e];
            int pos = atomicAdd(&g_off[d], 1);
            g_adj[pos] = src[e];
        }
        return;
    }
    int tile = bid - nfill;
    int tid = threadIdx.x;
    for (int i = tid; i < D_IN * D_H; i += 256) {
        int k = i >> 5, c = i & 31;
        sWp[(k >> 1) * 64 + c * 2 + (k & 1)] = W1[i];
    }
    int warp = tid >> 5, lane = tid & 31;
    int row0 = tile * 64 + warp * 8;
    #pragma unroll
    for (int r = 0; r < 8; r++) {
        int row = row0 + r;
        if (row < n)
            sx[warp][r][lane] = ((const float4*)(x + (size_t)row * D_IN))[lane];
    }
    __syncthreads();

    const ulonglong2* sxp = (const ulonglong2*)&sx[warp][0][0];
    const unsigned long long* sWq = (const unsigned long long*)sWp;
    unsigned long long acc[8] = {0ull,0ull,0ull,0ull,0ull,0ull,0ull,0ull};
    #pragma unroll 4
    for (int k4 = 0; k4 < D_IN / 4; k4++) {
        unsigned long long w01 = sWq[(k4 * 2 + 0) * 32 + lane];
        unsigned long long w23 = sWq[(k4 * 2 + 1) * 32 + lane];
        #pragma unroll
        for (int r = 0; r < 8; r++) {
            ulonglong2 xp = sxp[r * 32 + k4];
            asm("fma.rn.f32x2 %0, %1, %2, %0;" : "+l"(acc[r]) : "l"(xp.x), "l"(w01));
            asm("fma.rn.f32x2 %0, %1, %2, %0;" : "+l"(acc[r]) : "l"(xp.y), "l"(w23));
        }
    }
    #pragma unroll
    for (int r = 0; r < 8; r++) {
        int row = row0 + r;
        if (row < n) {
            float lo = __uint_as_float((unsigned)(acc[r] & 0xffffffffull));
            float hi = __uint_as_float((unsigned)(acc[r] >> 32));
            g_m1s[(size_t)row * D_H + lane] = (lo + hi) * g_dinv[row];
        }
    }
}

// ---- P5: fused layer-1 gather + layer-2 transform (R7 4-acc body) ----------
__global__ void __launch_bounds__(256) k_gather1(const float* __restrict__ b1,
                                                 const float* __restrict__ W2,
                                                 const float* __restrict__ b2,
                                                 float* __restrict__ out, int n) {
    int w = (int)((blockIdx.x * 256 + threadIdx.x) >> 5);
    int lane = threadIdx.x & 31;
    if (w >= n) return;
    int cnt = g_cnt[w];
    int start = g_off[w] - cnt;                 // off is END after fill
    float dv = g_dinv[w];

    float a0 = 0.f, a1 = 0.f, a2 = 0.f, a3 = 0.f;
    int j = 0;
    for (; j + 32 <= cnt; j += 32) {
        int idx = g_adj[start + j + lane];
        #pragma unroll
        for (int t = 0; t < 32; t += 4) {
            int s0 = __shfl_sync(0xffffffffu, idx, t + 0);
            int s1 = __shfl_sync(0xffffffffu, idx, t + 1);
            int s2 = __shfl_sync(0xffffffffu, idx, t + 2);
            int s3 = __shfl_sync(0xffffffffu, idx, t + 3);
            a0 += g_m1s[(size_t)s0 * D_H + lane];
            a1 += g_m1s[(size_t)s1 * D_H + lane];
            a2 += g_m1s[(size_t)s2 * D_H + lane];
            a3 += g_m1s[(size_t)s3 * D_H + lane];
        }
    }
    if (j < cnt) {
        int rem = cnt - j;
        int idx = (lane < rem) ? g_adj[start + j + lane] : 0;
        for (int t = 0; t < rem; t++) {
            int s = __shfl_sync(0xffffffffu, idx, t);
            a0 += g_m1s[(size_t)s * D_H + lane];
        }
    }
    float acc = (a0 + a1) + (a2 + a3);
    acc += g_m1s[(size_t)w * D_H + lane];          // self loop (m1s = m1*dinv)
    float h = fmaxf(acc * dv + __ldg(&b1[lane]), 0.f);
    float p0 = h * __ldg(&W2[lane * 2 + 0]);
    float p1 = h * __ldg(&W2[lane * 2 + 1]);
    #pragma unroll
    for (int o = 16; o; o >>= 1) {
        p0 += __shfl_xor_sync(0xffffffffu, p0, o);
        p1 += __shfl_xor_sync(0xffffffffu, p1, o);
    }
    if (lane == 0) {
        float q0 = p0 * dv, q1 = p1 * dv;
        g_p2[(size_t)w * 2 + 0] = q0;
        g_p2[(size_t)w * 2 + 1] = q1;
        out[(size_t)w * 2 + 0] = __ldg(&b2[0]) + q0 * dv;   // bias + self loop
        out[(size_t)w * 2 + 1] = __ldg(&b2[1]) + q1 * dv;
    }
}

// ---- P6: layer-2 gather ------------------------------------------------------
__global__ void __launch_bounds__(256) k_gather2(float* __restrict__ out, int n) {
    int w = (int)((blockIdx.x * 256 + threadIdx.x) >> 5);
    int lane = threadIdx.x & 31;
    if (w >= n) return;
    int cnt = g_cnt[w];
    int start = g_off[w] - cnt;
    float a0 = 0.f, a1 = 0.f;
    for (int j = lane; j < cnt; j += 32) {
        int s = g_adj[start + j];
        float2 p = *(const float2*)(g_p2 + (size_t)s * 2);
        a0 += p.x; a1 += p.y;
    }
    #pragma unroll
    for (int o = 16; o; o >>= 1) {
        a0 += __shfl_xor_sync(0xffffffffu, a0, o);
        a1 += __shfl_xor_sync(0xffffffffu, a1, o);
    }
    if (lane == 0) {
        float dv = g_dinv[w];
        out[(size_t)w * 2 + 0] += a0 * dv;
        out[(size_t)w * 2 + 1] += a1 * dv;
    }
}

extern "C" void kernel_launch(void* const* d_in, const int* in_sizes, int n_in,
                              void* d_out, int out_size) {
    const float* x   = (const float*)d_in[0];
    const int*   ei  = (const int*)d_in[1];
    const float* W1  = (const float*)d_in[2];
    const float* b1  = (const float*)d_in[3];
    const float* W2  = (const float*)d_in[4];
    const float* b2  = (const float*)d_in[5];
    float*       out = (float*)d_out;

    int n = in_sizes[0] / D_IN;
    int E = in_sizes[1] / 2;
    const int* src = ei;
    const int* dst = ei + E;

    int nb = (n + SCAN_BLK - 1) / SCAN_BLK;
    int n4 = (n + 3) / 4;
    int e4 = (E + 3) / 4;
    int ntile = (n + 63) / 64;
    int nfill = 512;                           // fill-role blocks

    k_zero    <<<(n4 + 255) / 256, 256>>>(n4);
    k_count   <<<(e4 + 255) / 256, 256>>>(dst, E);
    k_part    <<<nb, 256>>>(n);
    k_finoff  <<<(n + 255) / 256, 256>>>(n);
    k_fillgemm<<<nfill + ntile, 256>>>(src, dst, x, W1, n, E, nfill);
    k_gather1 <<<(n * 32 + 255) / 256, 256>>>(b1, W2, b2, out, n);
    k_gather2 <<<(n * 32 + 255) / 256, 256>>>(out, n);
}

// round 14
// speedup vs baseline: 1.3910x; 1.0416x over previous
#include <cuda_runtime.h>
#include <cuda_fp16.h>
#include <cstddef>

// GCN 2-layer: CSR build (ticket scan) + gather aggregation, fp16 messages.
// N=100000, E=3.2M, DIN=128, DH=32, DOUT=2. edge_index int32.

static constexpr int NMAX  = 100000;
static constexpr long long EMAX = 3300000;
static constexpr int D_IN  = 128;
static constexpr int D_H   = 32;
static constexpr int D_OUT = 2;
static constexpr int SCAN_BLK = 2048;

__device__ __align__(16) float  g_dinv[NMAX];
__device__ __align__(16) __half g_m1h [(size_t)NMAX * D_H];  // (x@W1)*dinv, fp16
__device__ __align__(16) float  g_p2  [(size_t)NMAX * D_OUT];
__device__ __align__(16) int    g_cnt[NMAX];
__device__ __align__(16) int    g_off[NMAX];    // exclusive start -> END after fill
__device__ int g_adj[EMAX];
__device__ int g_total;

// ---- P0: zero counts (int4) + ticket ----------------------------------------
__global__ void k_zero(int n4) {
    int i = blockIdx.x * blockDim.x + threadIdx.x;
    if (i < n4) ((int4*)g_cnt)[i] = make_int4(0, 0, 0, 0);
    if (i == 0) g_total = 0;
}

// ---- P1: count degrees (int4) ----------------------------------------------
__global__ void k_count(const int* __restrict__ dst, int E) {
    int i = blockIdx.x * blockDim.x + threadIdx.x;
    int e = i * 4;
    if (e + 3 < E) {
        int4 d = *(const int4*)(dst + e);
        atomicAdd(&g_cnt[d.x], 1);
        atomicAdd(&g_cnt[d.y], 1);
        atomicAdd(&g_cnt[d.z], 1);
        atomicAdd(&g_cnt[d.w], 1);
    } else {
        for (; e < E; e++) atomicAdd(&g_cnt[dst[e]], 1);
    }
}

// ---- P2: block-local scan + atomic ticket for region base + dinv -----------
// g_adj segment placement is arrival-order across scan blocks (legal for CSR).
__global__ void __launch_bounds__(256) k_scanoff(int n) {
    __shared__ int sp[256];
    __shared__ int sbase;
    int tid = threadIdx.x;
    int base = blockIdx.x * SCAN_BLK + tid * 8;
    int v[8]; int s = 0;
    #pragma unroll
    for (int j = 0; j < 8; j++) {
        int i = base + j;
        v[j] = (i < n) ? g_cnt[i] : 0;
        s += v[j];
    }
    sp[tid] = s; __syncthreads();
    for (int o = 1; o < 256; o <<= 1) {
        int t = (tid >= o) ? sp[tid - o] : 0;
        __syncthreads();
        sp[tid] += t;
        __syncthreads();
    }
    if (tid == 255) sbase = atomicAdd(&g_total, sp[255]);   // claim region
    __syncthreads();
    int excl = sbase + sp[tid] - s;      // exclusive prefix within block + base
    #pragma unroll
    for (int j = 0; j < 8; j++) {
        int i = base + j;
        if (i < n) {
            g_off[i]  = excl; excl += v[j];
            g_dinv[i] = rsqrtf((float)v[j] + 1.0f);   // +1 self loop
        }
    }
}

// ---- P3: fused CSR fill + layer-1 GEMM (disjoint data, block-role split) ---
__global__ void __launch_bounds__(256) k_fillgemm(const int* __restrict__ src,
                                                  const int* __restrict__ dst,
                                                  const float* __restrict__ x,
                                                  const float* __restrict__ W1,
                                                  int n, int E, int nfill) {
    __shared__ float  sWp[D_IN * D_H];       // k-pair interleaved W1^T
    __shared__ float4 sx[8][8][D_IN / 4];
    int bid = blockIdx.x;
    if (bid < nfill) {
        int nt = nfill * 256;
        for (int e = bid * 256 + threadIdx.x; e < E; e += nt) {
            int d = dst[e];
            int pos = atomicAdd(&g_off[d], 1);       // g_off -> END pointer
            g_adj[pos] = src[e];
        }
        return;
    }
    int tile = bid - nfill;
    int tid = threadIdx.x;
    for (int i = tid; i < D_IN * D_H; i += 256) {
        int k = i >> 5, c = i & 31;
        sWp[(k >> 1) * 64 + c * 2 + (k & 1)] = W1[i];
    }
    int warp = tid >> 5, lane = tid & 31;
    int row0 = tile * 64 + warp * 8;
    #pragma unroll
    for (int r = 0; r < 8; r++) {
        int row = row0 + r;
        if (row < n)
            sx[warp][r][lane] = ((const float4*)(x + (size_t)row * D_IN))[lane];
    }
    __syncthreads();

    const ulonglong2* sxp = (const ulonglong2*)&sx[warp][0][0];
    const unsigned long long* sWq = (const unsigned long long*)sWp;
    unsigned long long acc[8] = {0ull,0ull,0ull,0ull,0ull,0ull,0ull,0ull};
    #pragma unroll 4
    for (int k4 = 0; k4 < D_IN / 4; k4++) {
        unsigned long long w01 = sWq[(k4 * 2 + 0) * 32 + lane];
        unsigned long long w23 = sWq[(k4 * 2 + 1) * 32 + lane];
        #pragma unroll
        for (int r = 0; r < 8; r++) {
            ulonglong2 xp = sxp[r * 32 + k4];
            asm("fma.rn.f32x2 %0, %1, %2, %0;" : "+l"(acc[r]) : "l"(xp.x), "l"(w01));
            asm("fma.rn.f32x2 %0, %1, %2, %0;" : "+l"(acc[r]) : "l"(xp.y), "l"(w23));
        }
    }
    #pragma unroll
    for (int r = 0; r < 8; r++) {
        int row = row0 + r;
        if (row < n) {
            float lo = __uint_as_float((unsigned)(acc[r] & 0xffffffffull));
            float hi = __uint_as_float((unsigned)(acc[r] >> 32));
            float ms = (lo + hi) * g_dinv[row];
            g_m1h[(size_t)row * D_H + lane] = __float2half_rn(ms);
        }
    }
}

// ---- P4: fused layer-1 gather (fp16 msgs) + layer-2 transform ---------------
__global__ void __launch_bounds__(256) k_gather1(const float* __restrict__ b1,
                                                 const float* __restrict__ W2,
                                                 const float* __restrict__ b2,
                                                 float* __restrict__ out, int n) {
    int w = (int)((blockIdx.x * 256 + threadIdx.x) >> 5);
    int lane = threadIdx.x & 31;
    if (w >= n) return;
    int cnt = g_cnt[w];
    int start = g_off[w] - cnt;                 // off is END after fill
    float dv = g_dinv[w];

    float a0 = 0.f, a1 = 0.f, a2 = 0.f, a3 = 0.f;
    int j = 0;
    for (; j + 32 <= cnt; j += 32) {
        int idx = g_adj[start + j + lane];
        #pragma unroll
        for (int t = 0; t < 32; t += 4) {
            int s0 = __shfl_sync(0xffffffffu, idx, t + 0);
            int s1 = __shfl_sync(0xffffffffu, idx, t + 1);
            int s2 = __shfl_sync(0xffffffffu, idx, t + 2);
            int s3 = __shfl_sync(0xffffffffu, idx, t + 3);
            a0 += __half2float(g_m1h[(size_t)s0 * D_H + lane]);
            a1 += __half2float(g_m1h[(size_t)s1 * D_H + lane]);
            a2 += __half2float(g_m1h[(size_t)s2 * D_H + lane]);
            a3 += __half2float(g_m1h[(size_t)s3 * D_H + lane]);
        }
    }
    if (j < cnt) {
        int rem = cnt - j;
        int idx = (lane < rem) ? g_adj[start + j + lane] : 0;
        for (int t = 0; t < rem; t++) {
            int s = __shfl_sync(0xffffffffu, idx, t);
            a0 += __half2float(g_m1h[(size_t)s * D_H + lane]);
        }
    }
    float acc = (a0 + a1) + (a2 + a3);
    acc += __half2float(g_m1h[(size_t)w * D_H + lane]);   // self loop
    float h = fmaxf(acc * dv + __ldg(&b1[lane]), 0.f);
    float p0 = h * __ldg(&W2[lane * 2 + 0]);
    float p1 = h * __ldg(&W2[lane * 2 + 1]);
    #pragma unroll
    for (int o = 16; o; o >>= 1) {
        p0 += __shfl_xor_sync(0xffffffffu, p0, o);
        p1 += __shfl_xor_sync(0xffffffffu, p1, o);
    }
    if (lane == 0) {
        float q0 = p0 * dv, q1 = p1 * dv;
        g_p2[(size_t)w * 2 + 0] = q0;
        g_p2[(size_t)w * 2 + 1] = q1;
        out[(size_t)w * 2 + 0] = __ldg(&b2[0]) + q0 * dv;   // bias + self loop
        out[(size_t)w * 2 + 1] = __ldg(&b2[1]) + q1 * dv;
    }
}

// ---- P5: layer-2 gather ------------------------------------------------------
__global__ void __launch_bounds__(256) k_gather2(float* __restrict__ out, int n) {
    int w = (int)((blockIdx.x * 256 + threadIdx.x) >> 5);
    int lane = threadIdx.x & 31;
    if (w >= n) return;
    int cnt = g_cnt[w];
    int start = g_off[w] - cnt;
    float a0 = 0.f, a1 = 0.f;
    for (int j = lane; j < cnt; j += 32) {
        int s = g_adj[start + j];
        float2 p = *(const float2*)(g_p2 + (size_t)s * 2);
        a0 += p.x; a1 += p.y;
    }
    #pragma unroll
    for (int o = 16; o; o >>= 1) {
        a0 += __shfl_xor_sync(0xffffffffu, a0, o);
        a1 += __shfl_xor_sync(0xffffffffu, a1, o);
    }
    if (lane == 0) {
        float dv = g_dinv[w];
        out[(size_t)w * 2 + 0] += a0 * dv;
        out[(size_t)w * 2 + 1] += a1 * dv;
    }
}

extern "C" void kernel_launch(void* const* d_in, const int* in_sizes, int n_in,
                              void* d_out, int out_size) {
    const float* x   = (const float*)d_in[0];
    const int*   ei  = (const int*)d_in[1];
    const float* W1  = (const float*)d_in[2];
    const float* b1  = (const float*)d_in[3];
    const float* W2  = (const float*)d_in[4];
    const float* b2  = (const float*)d_in[5];
    float*       out = (float*)d_out;

    int n = in_sizes[0] / D_IN;
    int E = in_sizes[1] / 2;
    const int* src = ei;
    const int* dst = ei + E;

    int nb = (n + SCAN_BLK - 1) / SCAN_BLK;
    int n4 = (n + 3) / 4;
    int e4 = (E + 3) / 4;
    int ntile = (n + 63) / 64;
    int nfill = 512;

    k_zero    <<<(n4 + 255) / 256, 256>>>(n4);
    k_count   <<<(e4 + 255) / 256, 256>>>(dst, E);
    k_scanoff <<<nb, 256>>>(n);
    k_fillgemm<<<nfill + ntile, 256>>>(src, dst, x, W1, n, E, nfill);
    k_gather1 <<<(n * 32 + 255) / 256, 256>>>(b1, W2, b2, out, n);
    k_gather2 <<<(n * 32 + 255) / 256, 256>>>(out, n);
}